// round 12
// baseline (speedup 1.0000x reference)
#include <cuda_runtime.h>
#include <cuda_fp16.h>
#include <math.h>

#define NN 100000
#define EE 800000
#define DF 128
#define NB 391          // (NN+255)/256
#define FULLM 0xFFFFFFFFu

// ---------- scratch (no cudaMalloc allowed) ----------
__device__ __align__(16) __half2 g_hs[NN * (DF / 2)];  // h = x@W1 fp16 (25.6 MB)
__device__ __half  g_Wt[DF * DF];        // W1 transposed, fp16: [n][k]
__device__ float2 g_gs[NN];              // gs = (h2@W2)*dinv[row]
__device__ float  g_dinv[NN];
__device__ int    g_cnt[NN];             // in-degree (no self loop)
__device__ int    g_rowstart[NN];        // CSR offsets (by dst)
__device__ int    g_pos[NN];             // binning cursor
__device__ int    g_esrc[EE];            // src node per CSR slot
__device__ int    g_aggv[NB];            // lookback: block aggregate
__device__ int    g_incv[NB];            // lookback: inclusive prefix
__device__ int    g_flag[NB];            // lookback: 0=none,1=agg,2=inclusive

// ---------- side stream for GEMM overlap ----------
static cudaStream_t g_s2;
static cudaEvent_t g_ev1, g_ev2;
static struct StreamInit {
    StreamInit() {
        cudaStreamCreateWithFlags(&g_s2, cudaStreamNonBlocking);
        cudaEventCreateWithFlags(&g_ev1, cudaEventDisableTiming);
        cudaEventCreateWithFlags(&g_ev2, cudaEventDisableTiming);
    }
} g_stream_init;

// ---------- degree ----------
__global__ void k_zero_cnt() {
    int i = blockIdx.x * blockDim.x + threadIdx.x;
    if (i < NN) g_cnt[i] = 0;
}

__global__ void k_count(const int* __restrict__ dst) {
    int e = blockIdx.x * blockDim.x + threadIdx.x;
    if (e < NB) g_flag[e] = 0;               // reset lookback flags each call
    if (e < EE) atomicAdd(&g_cnt[dst[e]], 1);
}

// ---------- single-pass scan (decoupled lookback) + dinv + pos + gs zero ----------
__global__ __launch_bounds__(256) void k_scan() {
    __shared__ int sh_warp[8];
    __shared__ int sh_prefix;
    int b = blockIdx.x, t = threadIdx.x, i = b * 256 + t;
    int lane = t & 31, wid = t >> 5;
    int v = (i < NN) ? g_cnt[i] : 0;

    int s = v;
#pragma unroll
    for (int o = 1; o < 32; o <<= 1) {
        int x = __shfl_up_sync(FULLM, s, o);
        if (lane >= o) s += x;
    }
    if (lane == 31) sh_warp[wid] = s;
    __syncthreads();
    if (t < 8) {
        int ws = sh_warp[t];
#pragma unroll
        for (int o = 1; o < 8; o <<= 1) {
            int x = __shfl_up_sync(0xFFu, ws, o);
            if (t >= o) ws += x;
        }
        sh_warp[t] = ws;
    }
    __syncthreads();
    int incl = s + (wid ? sh_warp[wid - 1] : 0);
    int btot = sh_warp[7];

    if (t == 0) {
        g_aggv[b] = btot;
        __threadfence();
        ((volatile int*)g_flag)[b] = 1;
    }

    if (t < 32) {
        int running = 0;
        if (b > 0) {
            int base = b - 1;
            while (true) {
                int idx = base - t;
                int f;
                do {
                    f = (idx >= 0) ? ((volatile int*)g_flag)[idx] : 2;
                } while (__ballot_sync(FULLM, f == 0));
                __threadfence();
                unsigned m2 = __ballot_sync(FULLM, f == 2);
                int val = 0;
                if (m2) {
                    int L = __ffs(m2) - 1;
                    if (t < L) val = ((volatile int*)g_aggv)[idx];
                    else if (t == L) val = (idx >= 0) ? ((volatile int*)g_incv)[idx] : 0;
                } else {
                    val = ((volatile int*)g_aggv)[idx];
                }
#pragma unroll
                for (int o = 16; o > 0; o >>= 1) val += __shfl_xor_sync(FULLM, val, o);
                running += val;
                if (m2) break;
                base -= 32;
            }
        }
        if (t == 0) {
            g_incv[b] = running + btot;
            __threadfence();
            ((volatile int*)g_flag)[b] = 2;
            sh_prefix = running;
        }
    }
    __syncthreads();

    if (i < NN) {
        int rs = sh_prefix + incl - v;
        g_rowstart[i] = rs;
        g_pos[i] = rs;
        g_dinv[i] = rsqrtf(1.0f + (float)v);
        g_gs[i] = make_float2(0.f, 0.f);   // cleared for agg_mid's red.add
    }
}

__global__ void k_bin(const int* __restrict__ src, const int* __restrict__ dst) {
    int e = blockIdx.x * blockDim.x + threadIdx.x;
    if (e < EE) {
        int d = dst[e];
        int p = atomicAdd(&g_pos[d], 1);
        g_esrc[p] = src[e];
    }
}

// ---------- W1 transpose + fp16 convert: g_Wt[n][k] = fp16(W1[k][n]) ----------
__global__ void k_wprep(const float* __restrict__ W1) {
    int tid = blockIdx.x * 256 + threadIdx.x;   // 16384
    int n = tid >> 7, k = tid & 127;
    g_Wt[n * DF + k] = __float2half(W1[(size_t)k * DF + n]);
}

// ---------- fp16 tensor-core GEMM1: g_hs = fp16(x @ W1) ----------
__device__ __forceinline__ void mma_f16(float* c, const unsigned* a, const unsigned* b) {
    asm volatile(
        "mma.sync.aligned.m16n8k16.row.col.f32.f16.f16.f32 "
        "{%0,%1,%2,%3}, {%4,%5,%6,%7}, {%8,%9}, {%0,%1,%2,%3};"
        : "+f"(c[0]), "+f"(c[1]), "+f"(c[2]), "+f"(c[3])
        : "r"(a[0]), "r"(a[1]), "r"(a[2]), "r"(a[3]), "r"(b[0]), "r"(b[1]));
}

#define XS_STR 40
#define WS_STR 136

__global__ __launch_bounds__(256, 2) void k_gemm1(const float* __restrict__ X) {
    __shared__ __half Xs[128][XS_STR];
    __shared__ __half Ws[128][WS_STR];

    const int t = threadIdx.x;
    const int m0 = blockIdx.x * 128;
    const int w = t >> 5, lane = t & 31;
    const int m0w = (w >> 2) * 64;
    const int n0w = (w & 3) * 32;
    const int lg = lane >> 2, lq = lane & 3;

#pragma unroll
    for (int i = 0; i < 8; i++) {
        int g = i * 256 + t;
        int row = g >> 4, c = (g & 15) * 8;
        *(uint4*)&Ws[row][c] = *(const uint4*)&g_Wt[row * DF + c];
    }

    float acc[4][4][4] = {};
    float4 pv[4];

    auto prefetch = [&](int kc) {
#pragma unroll
        for (int i = 0; i < 4; i++) {
            int g = i * 256 + t;
            int row = g >> 3, q = g & 7;
            int m = m0 + row;
            pv[i] = (m < NN) ? *(const float4*)&X[(size_t)m * DF + kc * 32 + q * 4]
                             : make_float4(0.f, 0.f, 0.f, 0.f);
        }
    };

    prefetch(0);
    __syncthreads();

    for (int kc = 0; kc < 4; kc++) {
#pragma unroll
        for (int i = 0; i < 4; i++) {
            int g = i * 256 + t;
            int row = g >> 3, q = g & 7;
            __half2 h0 = __floats2half2_rn(pv[i].x, pv[i].y);
            __half2 h1 = __floats2half2_rn(pv[i].z, pv[i].w);
            uint2 u;
            u.x = *(unsigned*)&h0;
            u.y = *(unsigned*)&h1;
            *(uint2*)&Xs[row][q * 4] = u;
        }
        __syncthreads();
        if (kc < 3) prefetch(kc + 1);

#pragma unroll
        for (int k0 = 0; k0 < 32; k0 += 16) {
            int kg = kc * 32 + k0;
            unsigned A[4][4], B[4][2];
#pragma unroll
            for (int mi = 0; mi < 4; mi++) {
                int mr = m0w + mi * 16 + lg;
                A[mi][0] = *(unsigned*)&Xs[mr][k0 + 2 * lq];
                A[mi][1] = *(unsigned*)&Xs[mr + 8][k0 + 2 * lq];
                A[mi][2] = *(unsigned*)&Xs[mr][k0 + 8 + 2 * lq];
                A[mi][3] = *(unsigned*)&Xs[mr + 8][k0 + 8 + 2 * lq];
            }
#pragma unroll
            for (int ni = 0; ni < 4; ni++) {
                int nc = n0w + ni * 8 + lg;
                B[ni][0] = *(unsigned*)&Ws[nc][kg + 2 * lq];
                B[ni][1] = *(unsigned*)&Ws[nc][kg + 8 + 2 * lq];
            }
#pragma unroll
            for (int mi = 0; mi < 4; mi++)
#pragma unroll
                for (int ni = 0; ni < 4; ni++)
                    mma_f16(acc[mi][ni], A[mi], B[ni]);
        }
        __syncthreads();
    }

#pragma unroll
    for (int mi = 0; mi < 4; mi++) {
        int r0 = m0 + m0w + mi * 16 + lg;
        int r1 = r0 + 8;
#pragma unroll
        for (int ni = 0; ni < 4; ni++) {
            int h2col = ((n0w + ni * 8) >> 1) + lq;
            if (r0 < NN)
                g_hs[(size_t)r0 * (DF / 2) + h2col] =
                    __floats2half2_rn(acc[mi][ni][0], acc[mi][ni][1]);
            if (r1 < NN)
                g_hs[(size_t)r1 * (DF / 2) + h2col] =
                    __floats2half2_rn(acc[mi][ni][2], acc[mi][ni][3]);
        }
    }
}

// ---------- fused gather-aggregate + relu + W2 GEMV (layer 1 -> gs) ----------
// TWO warps per dst node: warp-half wh in {0,1} owns 64 features.
// Each lane owns 2 features (one half2 = 4B load). 2x resident warps for
// latency hiding; partial W2 dot merged via red.global.add.v2.f32.
__global__ __launch_bounds__(256) void k_agg_mid(const float* __restrict__ b1,
                                                 const float* __restrict__ W2) {
    int gw = (blockIdx.x * 256 + threadIdx.x) >> 5;   // global warp id
    int lane = threadIdx.x & 31;
    int r = gw >> 1, wh = gw & 1;
    if (r >= NN) return;

    const unsigned* hsw = (const unsigned*)g_hs;      // 64 half2-words per row
    const int fcol = wh * 32 + lane;                  // half2 column (0..63)
    float di = g_dinv[r];

    unsigned sv = hsw[(size_t)r * 64 + fcol];
    float2 sf = __half22float2(*(__half2*)&sv);
    float ax = sf.x * di, ay = sf.y * di;

    int start = g_rowstart[r];
    int len = g_cnt[r];
    for (int j0 = 0; j0 < len; j0 += 32) {
        int cnt = min(32, len - j0);
        int sidx = 0;
        float sd = 0.f;
        if (lane < cnt) {
            sidx = g_esrc[start + j0 + lane];
            sd = g_dinv[sidx];
        }
#pragma unroll 4
        for (int j = 0; j < cnt; j++) {
            int s = __shfl_sync(FULLM, sidx, j);
            float d = __shfl_sync(FULLM, sd, j);
            unsigned v = hsw[(size_t)s * 64 + fcol];
            float2 f = __half22float2(*(__half2*)&v);
            ax = fmaf(f.x, d, ax);
            ay = fmaf(f.y, d, ay);
        }
    }

    // bias + relu on this warp's 2 features, partial W2 GEMV
    int feat = fcol * 2;                              // feature index (0..126)
    float2 bb = *(const float2*)&b1[feat];
    float h0 = fmaxf(fmaf(di, ax, bb.x), 0.f);
    float h1 = fmaxf(fmaf(di, ay, bb.y), 0.f);
    float2 w0 = ((const float2*)W2)[feat];
    float2 w1 = ((const float2*)W2)[feat + 1];
    float gx = h0 * w0.x + h1 * w1.x;
    float gy = h0 * w0.y + h1 * w1.y;
#pragma unroll
    for (int off = 16; off > 0; off >>= 1) {
        gx += __shfl_xor_sync(FULLM, gx, off);
        gy += __shfl_xor_sync(FULLM, gy, off);
    }
    if (lane == 0) {
        float* p = (float*)&g_gs[r];
        float vx = gx * di, vy = gy * di;
        asm volatile("red.global.add.v2.f32 [%0], {%1, %2};"
                     :: "l"(p), "f"(vx), "f"(vy) : "memory");
    }
}

// ---------- layer-2 gather + bias -> out ----------
__global__ __launch_bounds__(256) void k_agg2(const float* __restrict__ b2,
                                              float* __restrict__ out) {
    int gt = blockIdx.x * 256 + threadIdx.x;
    int r = gt >> 5, lane = gt & 31;
    if (r >= NN) return;

    int start = g_rowstart[r];
    int len = g_cnt[r];
    float ax = 0.f, ay = 0.f;
    for (int j = lane; j < len; j += 32) {
        int s = g_esrc[start + j];
        float2 v = g_gs[s];
        ax += v.x; ay += v.y;
    }
#pragma unroll
    for (int off = 16; off > 0; off >>= 1) {
        ax += __shfl_xor_sync(FULLM, ax, off);
        ay += __shfl_xor_sync(FULLM, ay, off);
    }
    if (lane == 0) {
        float di = g_dinv[r];
        float2 self = g_gs[r];
        float2 o = make_float2(fmaf(di, self.x + ax, __ldg(&b2[0])),
                               fmaf(di, self.y + ay, __ldg(&b2[1])));
        *(float2*)&out[(size_t)r * 2] = o;
    }
}

extern "C" void kernel_launch(void* const* d_in, const int* in_sizes, int n_in,
                              void* d_out, int out_size) {
    const float* x  = (const float*)d_in[0];
    const int*   ei = (const int*)d_in[1];
    const float* W1 = (const float*)d_in[2];
    const float* b1 = (const float*)d_in[3];
    const float* W2 = (const float*)d_in[4];
    const float* b2 = (const float*)d_in[5];
    const int* src = ei;        // edge_index[0, :]
    const int* dst = ei + EE;   // edge_index[1, :]

    // fork point for side stream
    cudaEventRecord(g_ev1, 0);
    cudaStreamWaitEvent(g_s2, g_ev1, 0);

    // submission order puts k_gemm1 at position 4 (ncu captures launch #4)
    k_zero_cnt<<<NB, 256>>>();                       // 1 (main)
    k_count<<<(EE + 255) / 256, 256>>>(dst);         // 2 (main)
    k_wprep<<<64, 256, 0, g_s2>>>(W1);               // 3 (s2)
    k_gemm1<<<(NN + 127) / 128, 256, 0, g_s2>>>(x);  // 4 (s2)  <- profiled
    cudaEventRecord(g_ev2, g_s2);
    k_scan<<<NB, 256>>>();                           // 5 (main)
    k_bin<<<(EE + 255) / 256, 256>>>(src, dst);      // 6 (main)

    // join, then fused aggregation (2 warps per node)
    cudaStreamWaitEvent(0, g_ev2, 0);
    k_agg_mid<<<(NN * 2 * 32 + 255) / 256, 256>>>(b1, W2);       // 7
    k_agg2<<<(NN * 32 + 255) / 256, 256>>>(b2, (float*)d_out);   // 8
}

// round 13
// speedup vs baseline: 1.2182x; 1.2182x over previous
#include <cuda_runtime.h>
#include <cuda_fp16.h>
#include <math.h>

#define NN 100000
#define EE 800000
#define DF 128
#define NB 391          // (NN+255)/256
#define FULLM 0xFFFFFFFFu

// ---------- scratch (no cudaMalloc allowed) ----------
__device__ __align__(16) __half2 g_hs[NN * (DF / 2)];  // h = x@W1 fp16 (25.6 MB)
__device__ __half  g_Wt[DF * DF];        // W1 transposed, fp16: [n][k]
__device__ float2 g_gs[NN];              // gs = (h2@W2)*dinv[row]
__device__ float  g_dinv[NN];
__device__ int    g_cnt[NN];             // in-degree (no self loop)
__device__ int    g_rowstart[NN];        // CSR offsets (by dst)
__device__ int    g_pos[NN];             // binning cursor
__device__ int    g_esrc[EE];            // src node per CSR slot
__device__ int    g_aggv[NB];            // lookback: block aggregate
__device__ int    g_incv[NB];            // lookback: inclusive prefix
__device__ int    g_flag[NB];            // lookback: 0=none,1=agg,2=inclusive

// ---------- side stream for GEMM overlap ----------
static cudaStream_t g_s2;
static cudaEvent_t g_ev1, g_ev2;
static struct StreamInit {
    StreamInit() {
        cudaStreamCreateWithFlags(&g_s2, cudaStreamNonBlocking);
        cudaEventCreateWithFlags(&g_ev1, cudaEventDisableTiming);
        cudaEventCreateWithFlags(&g_ev2, cudaEventDisableTiming);
    }
} g_stream_init;

// ---------- degree ----------
__global__ void k_zero_cnt() {
    int i = blockIdx.x * blockDim.x + threadIdx.x;
    if (i < NN) g_cnt[i] = 0;
}

__global__ void k_count(const int* __restrict__ dst) {
    int e = blockIdx.x * blockDim.x + threadIdx.x;
    if (e < NB) g_flag[e] = 0;               // reset lookback flags each call
    if (e < EE) atomicAdd(&g_cnt[dst[e]], 1);
}

// ---------- single-pass scan (decoupled lookback) + dinv + pos ----------
__global__ __launch_bounds__(256) void k_scan() {
    __shared__ int sh_warp[8];
    __shared__ int sh_prefix;
    int b = blockIdx.x, t = threadIdx.x, i = b * 256 + t;
    int lane = t & 31, wid = t >> 5;
    int v = (i < NN) ? g_cnt[i] : 0;

    int s = v;
#pragma unroll
    for (int o = 1; o < 32; o <<= 1) {
        int x = __shfl_up_sync(FULLM, s, o);
        if (lane >= o) s += x;
    }
    if (lane == 31) sh_warp[wid] = s;
    __syncthreads();
    if (t < 8) {
        int ws = sh_warp[t];
#pragma unroll
        for (int o = 1; o < 8; o <<= 1) {
            int x = __shfl_up_sync(0xFFu, ws, o);
            if (t >= o) ws += x;
        }
        sh_warp[t] = ws;
    }
    __syncthreads();
    int incl = s + (wid ? sh_warp[wid - 1] : 0);
    int btot = sh_warp[7];

    if (t == 0) {
        g_aggv[b] = btot;
        __threadfence();
        ((volatile int*)g_flag)[b] = 1;
    }

    if (t < 32) {
        int running = 0;
        if (b > 0) {
            int base = b - 1;
            while (true) {
                int idx = base - t;
                int f;
                do {
                    f = (idx >= 0) ? ((volatile int*)g_flag)[idx] : 2;
                } while (__ballot_sync(FULLM, f == 0));
                __threadfence();
                unsigned m2 = __ballot_sync(FULLM, f == 2);
                int val = 0;
                if (m2) {
                    int L = __ffs(m2) - 1;
                    if (t < L) val = ((volatile int*)g_aggv)[idx];
                    else if (t == L) val = (idx >= 0) ? ((volatile int*)g_incv)[idx] : 0;
                } else {
                    val = ((volatile int*)g_aggv)[idx];
                }
#pragma unroll
                for (int o = 16; o > 0; o >>= 1) val += __shfl_xor_sync(FULLM, val, o);
                running += val;
                if (m2) break;
                base -= 32;
            }
        }
        if (t == 0) {
            g_incv[b] = running + btot;
            __threadfence();
            ((volatile int*)g_flag)[b] = 2;
            sh_prefix = running;
        }
    }
    __syncthreads();

    if (i < NN) {
        int rs = sh_prefix + incl - v;
        g_rowstart[i] = rs;
        g_pos[i] = rs;
        g_dinv[i] = rsqrtf(1.0f + (float)v);
    }
}

__global__ void k_bin(const int* __restrict__ src, const int* __restrict__ dst) {
    int e = blockIdx.x * blockDim.x + threadIdx.x;
    if (e < EE) {
        int d = dst[e];
        int p = atomicAdd(&g_pos[d], 1);
        g_esrc[p] = src[e];
    }
}

// ---------- W1 transpose + fp16 convert: g_Wt[n][k] = fp16(W1[k][n]) ----------
__global__ void k_wprep(const float* __restrict__ W1) {
    int tid = blockIdx.x * 256 + threadIdx.x;   // 16384
    int n = tid >> 7, k = tid & 127;
    g_Wt[n * DF + k] = __float2half(W1[(size_t)k * DF + n]);
}

// ---------- fp16 tensor-core GEMM1: g_hs = fp16(x @ W1) ----------
__device__ __forceinline__ void mma_f16(float* c, const unsigned* a, const unsigned* b) {
    asm volatile(
        "mma.sync.aligned.m16n8k16.row.col.f32.f16.f16.f32 "
        "{%0,%1,%2,%3}, {%4,%5,%6,%7}, {%8,%9}, {%0,%1,%2,%3};"
        : "+f"(c[0]), "+f"(c[1]), "+f"(c[2]), "+f"(c[3])
        : "r"(a[0]), "r"(a[1]), "r"(a[2]), "r"(a[3]), "r"(b[0]), "r"(b[1]));
}

#define XS_STR 40
#define WS_STR 136

__global__ __launch_bounds__(256, 2) void k_gemm1(const float* __restrict__ X) {
    __shared__ __half Xs[128][XS_STR];
    __shared__ __half Ws[128][WS_STR];

    const int t = threadIdx.x;
    const int m0 = blockIdx.x * 128;
    const int w = t >> 5, lane = t & 31;
    const int m0w = (w >> 2) * 64;
    const int n0w = (w & 3) * 32;
    const int lg = lane >> 2, lq = lane & 3;

#pragma unroll
    for (int i = 0; i < 8; i++) {
        int g = i * 256 + t;
        int row = g >> 4, c = (g & 15) * 8;
        *(uint4*)&Ws[row][c] = *(const uint4*)&g_Wt[row * DF + c];
    }

    float acc[4][4][4] = {};
    float4 pv[4];

    auto prefetch = [&](int kc) {
#pragma unroll
        for (int i = 0; i < 4; i++) {
            int g = i * 256 + t;
            int row = g >> 3, q = g & 7;
            int m = m0 + row;
            pv[i] = (m < NN) ? *(const float4*)&X[(size_t)m * DF + kc * 32 + q * 4]
                             : make_float4(0.f, 0.f, 0.f, 0.f);
        }
    };

    prefetch(0);
    __syncthreads();

    for (int kc = 0; kc < 4; kc++) {
#pragma unroll
        for (int i = 0; i < 4; i++) {
            int g = i * 256 + t;
            int row = g >> 3, q = g & 7;
            __half2 h0 = __floats2half2_rn(pv[i].x, pv[i].y);
            __half2 h1 = __floats2half2_rn(pv[i].z, pv[i].w);
            uint2 u;
            u.x = *(unsigned*)&h0;
            u.y = *(unsigned*)&h1;
            *(uint2*)&Xs[row][q * 4] = u;
        }
        __syncthreads();
        if (kc < 3) prefetch(kc + 1);

#pragma unroll
        for (int k0 = 0; k0 < 32; k0 += 16) {
            int kg = kc * 32 + k0;
            unsigned A[4][4], B[4][2];
#pragma unroll
            for (int mi = 0; mi < 4; mi++) {
                int mr = m0w + mi * 16 + lg;
                A[mi][0] = *(unsigned*)&Xs[mr][k0 + 2 * lq];
                A[mi][1] = *(unsigned*)&Xs[mr + 8][k0 + 2 * lq];
                A[mi][2] = *(unsigned*)&Xs[mr][k0 + 8 + 2 * lq];
                A[mi][3] = *(unsigned*)&Xs[mr + 8][k0 + 8 + 2 * lq];
            }
#pragma unroll
            for (int ni = 0; ni < 4; ni++) {
                int nc = n0w + ni * 8 + lg;
                B[ni][0] = *(unsigned*)&Ws[nc][kg + 2 * lq];
                B[ni][1] = *(unsigned*)&Ws[nc][kg + 8 + 2 * lq];
            }
#pragma unroll
            for (int mi = 0; mi < 4; mi++)
#pragma unroll
                for (int ni = 0; ni < 4; ni++)
                    mma_f16(acc[mi][ni], A[mi], B[ni]);
        }
        __syncthreads();
    }

#pragma unroll
    for (int mi = 0; mi < 4; mi++) {
        int r0 = m0 + m0w + mi * 16 + lg;
        int r1 = r0 + 8;
#pragma unroll
        for (int ni = 0; ni < 4; ni++) {
            int h2col = ((n0w + ni * 8) >> 1) + lq;
            if (r0 < NN)
                g_hs[(size_t)r0 * (DF / 2) + h2col] =
                    __floats2half2_rn(acc[mi][ni][0], acc[mi][ni][1]);
            if (r1 < NN)
                g_hs[(size_t)r1 * (DF / 2) + h2col] =
                    __floats2half2_rn(acc[mi][ni][2], acc[mi][ni][3]);
        }
    }
}

// ---------- fused gather-aggregate + relu + W2 GEMV (layer 1 -> gs) ----------
// one warp per dst node; each lane owns 4 features (uint2 = 4 halves).
// NO shuffles: edge index + dinv read as uniform (broadcast) loads; every
// edge iteration fully independent -> deep software pipelining.
__global__ __launch_bounds__(256) void k_agg_mid(const float* __restrict__ b1,
                                                 const float* __restrict__ W2) {
    int gt = blockIdx.x * 256 + threadIdx.x;
    int r = gt >> 5, lane = gt & 31;
    if (r >= NN) return;

    const uint2* hsv = (const uint2*)g_hs;   // 32 uint2 per row
    float di = g_dinv[r];

    uint2 sv = hsv[(size_t)r * 32 + lane];
    float2 s0 = __half22float2(*(__half2*)&sv.x);
    float2 s1 = __half22float2(*(__half2*)&sv.y);
    float ax = s0.x * di, ay = s0.y * di, az = s1.x * di, aw = s1.y * di;

    int start = g_rowstart[r];
    int end = start + g_cnt[r];
#pragma unroll 4
    for (int j = start; j < end; j++) {
        int s = __ldg(&g_esrc[j]);        // uniform: all lanes same addr
        float d = __ldg(&g_dinv[s]);      // uniform
        uint2 v = hsv[(size_t)s * 32 + lane];
        float2 f0 = __half22float2(*(__half2*)&v.x);
        float2 f1 = __half22float2(*(__half2*)&v.y);
        ax = fmaf(f0.x, d, ax);
        ay = fmaf(f0.y, d, ay);
        az = fmaf(f1.x, d, az);
        aw = fmaf(f1.y, d, aw);
    }

    float4 bb = *(const float4*)&b1[lane * 4];
    float h0 = fmaxf(fmaf(di, ax, bb.x), 0.f);
    float h1 = fmaxf(fmaf(di, ay, bb.y), 0.f);
    float h2 = fmaxf(fmaf(di, az, bb.z), 0.f);
    float h3 = fmaxf(fmaf(di, aw, bb.w), 0.f);

    float2 w0 = *(const float2*)&W2[(size_t)(lane * 4 + 0) * 2];
    float2 w1 = *(const float2*)&W2[(size_t)(lane * 4 + 1) * 2];
    float2 w2 = *(const float2*)&W2[(size_t)(lane * 4 + 2) * 2];
    float2 w3 = *(const float2*)&W2[(size_t)(lane * 4 + 3) * 2];
    float gx = h0 * w0.x + h1 * w1.x + h2 * w2.x + h3 * w3.x;
    float gy = h0 * w0.y + h1 * w1.y + h2 * w2.y + h3 * w3.y;
#pragma unroll
    for (int off = 16; off > 0; off >>= 1) {
        gx += __shfl_xor_sync(FULLM, gx, off);
        gy += __shfl_xor_sync(FULLM, gy, off);
    }
    if (lane == 0) g_gs[r] = make_float2(gx * di, gy * di);
}

// ---------- layer-2 gather + bias -> out ----------
__global__ __launch_bounds__(256) void k_agg2(const float* __restrict__ b2,
                                              float* __restrict__ out) {
    int gt = blockIdx.x * 256 + threadIdx.x;
    int r = gt >> 5, lane = gt & 31;
    if (r >= NN) return;

    int start = g_rowstart[r];
    int len = g_cnt[r];
    float ax = 0.f, ay = 0.f;
    for (int j = lane; j < len; j += 32) {
        int s = g_esrc[start + j];
        float2 v = g_gs[s];
        ax += v.x; ay += v.y;
    }
#pragma unroll
    for (int off = 16; off > 0; off >>= 1) {
        ax += __shfl_xor_sync(FULLM, ax, off);
        ay += __shfl_xor_sync(FULLM, ay, off);
    }
    if (lane == 0) {
        float di = g_dinv[r];
        float2 self = g_gs[r];
        float2 o = make_float2(fmaf(di, self.x + ax, __ldg(&b2[0])),
                               fmaf(di, self.y + ay, __ldg(&b2[1])));
        *(float2*)&out[(size_t)r * 2] = o;
    }
}

extern "C" void kernel_launch(void* const* d_in, const int* in_sizes, int n_in,
                              void* d_out, int out_size) {
    const float* x  = (const float*)d_in[0];
    const int*   ei = (const int*)d_in[1];
    const float* W1 = (const float*)d_in[2];
    const float* b1 = (const float*)d_in[3];
    const float* W2 = (const float*)d_in[4];
    const float* b2 = (const float*)d_in[5];
    const int* src = ei;        // edge_index[0, :]
    const int* dst = ei + EE;   // edge_index[1, :]

    // fork point for side stream (GEMM branch independent of graph structure)
    cudaEventRecord(g_ev1, 0);
    cudaStreamWaitEvent(g_s2, g_ev1, 0);

    // submission order makes k_count the 4th launch (ncu captures #4)
    k_zero_cnt<<<NB, 256>>>();                       // 1 (main)
    k_wprep<<<64, 256, 0, g_s2>>>(W1);               // 2 (s2)
    k_gemm1<<<(NN + 127) / 128, 256, 0, g_s2>>>(x);  // 3 (s2)
    cudaEventRecord(g_ev2, g_s2);
    k_count<<<(EE + 255) / 256, 256>>>(dst);         // 4 (main)  <- profiled
    k_scan<<<NB, 256>>>();                           // 5 (main)
    k_bin<<<(EE + 255) / 256, 256>>>(src, dst);      // 6 (main)

    // join, then fused aggregation
    cudaStreamWaitEvent(0, g_ev2, 0);
    k_agg_mid<<<(NN * 32 + 255) / 256, 256>>>(b1, W2);           // 7
    k_agg2<<<(NN * 32 + 255) / 256, 256>>>(b2, (float*)d_out);   // 8
}

// round 15
// speedup vs baseline: 1.2817x; 1.0521x over previous
#include <cuda_runtime.h>
#include <cuda_fp16.h>
#include <math.h>

#define NN 100000
#define EE 800000
#define DF 128
#define NB 391          // (NN+255)/256
#define FULLM 0xFFFFFFFFu

// ---------- scratch (no cudaMalloc allowed) ----------
__device__ __align__(16) __half2 g_hs[NN * (DF / 2)];  // h = x@W1 fp16 (25.6 MB)
__device__ __half  g_Wt[DF * DF];        // W1 transposed, fp16: [n][k]
__device__ float2 g_gs[NN];              // gs = (h2@W2)*dinv[row]
__device__ float  g_dinv[NN];
__device__ int    g_cnt[NN];             // in-degree (no self loop)
__device__ int    g_rowstart[NN];        // CSR offsets (by dst)
__device__ int    g_pos[NN];             // binning cursor
__device__ int    g_esrc[EE];            // src node per CSR slot
__device__ int    g_aggv[NB];            // lookback: block aggregate
__device__ int    g_incv[NB];            // lookback: inclusive prefix
__device__ int    g_flag[NB];            // lookback: 0=none,1=agg,2=inclusive

// ---------- side stream for GEMM overlap ----------
static cudaStream_t g_s2;
static cudaEvent_t g_ev1, g_ev2;
static struct StreamInit {
    StreamInit() {
        cudaStreamCreateWithFlags(&g_s2, cudaStreamNonBlocking);
        cudaEventCreateWithFlags(&g_ev1, cudaEventDisableTiming);
        cudaEventCreateWithFlags(&g_ev2, cudaEventDisableTiming);
    }
} g_stream_init;

// ---------- degree ----------
__global__ void k_zero_cnt() {
    int i = blockIdx.x * blockDim.x + threadIdx.x;
    if (i < NN) g_cnt[i] = 0;
}

__global__ void k_count(const int* __restrict__ dst) {
    int e = blockIdx.x * blockDim.x + threadIdx.x;
    if (e < NB) g_flag[e] = 0;               // reset lookback flags each call
    if (e < EE) atomicAdd(&g_cnt[dst[e]], 1);
}

// ---------- single-pass scan (decoupled lookback) + dinv + pos ----------
__global__ __launch_bounds__(256) void k_scan() {
    __shared__ int sh_warp[8];
    __shared__ int sh_prefix;
    int b = blockIdx.x, t = threadIdx.x, i = b * 256 + t;
    int lane = t & 31, wid = t >> 5;
    int v = (i < NN) ? g_cnt[i] : 0;

    int s = v;
#pragma unroll
    for (int o = 1; o < 32; o <<= 1) {
        int x = __shfl_up_sync(FULLM, s, o);
        if (lane >= o) s += x;
    }
    if (lane == 31) sh_warp[wid] = s;
    __syncthreads();
    if (t < 8) {
        int ws = sh_warp[t];
#pragma unroll
        for (int o = 1; o < 8; o <<= 1) {
            int x = __shfl_up_sync(0xFFu, ws, o);
            if (t >= o) ws += x;
        }
        sh_warp[t] = ws;
    }
    __syncthreads();
    int incl = s + (wid ? sh_warp[wid - 1] : 0);
    int btot = sh_warp[7];

    if (t == 0) {
        g_aggv[b] = btot;
        __threadfence();
        ((volatile int*)g_flag)[b] = 1;
    }

    if (t < 32) {
        int running = 0;
        if (b > 0) {
            int base = b - 1;
            while (true) {
                int idx = base - t;
                int f;
                do {
                    f = (idx >= 0) ? ((volatile int*)g_flag)[idx] : 2;
                } while (__ballot_sync(FULLM, f == 0));
                __threadfence();
                unsigned m2 = __ballot_sync(FULLM, f == 2);
                int val = 0;
                if (m2) {
                    int L = __ffs(m2) - 1;
                    if (t < L) val = ((volatile int*)g_aggv)[idx];
                    else if (t == L) val = (idx >= 0) ? ((volatile int*)g_incv)[idx] : 0;
                } else {
                    val = ((volatile int*)g_aggv)[idx];
                }
#pragma unroll
                for (int o = 16; o > 0; o >>= 1) val += __shfl_xor_sync(FULLM, val, o);
                running += val;
                if (m2) break;
                base -= 32;
            }
        }
        if (t == 0) {
            g_incv[b] = running + btot;
            __threadfence();
            ((volatile int*)g_flag)[b] = 2;
            sh_prefix = running;
        }
    }
    __syncthreads();

    if (i < NN) {
        int rs = sh_prefix + incl - v;
        g_rowstart[i] = rs;
        g_pos[i] = rs;
        g_dinv[i] = rsqrtf(1.0f + (float)v);
    }
}

__global__ void k_bin(const int* __restrict__ src, const int* __restrict__ dst) {
    int e = blockIdx.x * blockDim.x + threadIdx.x;
    if (e < EE) {
        int d = dst[e];
        int p = atomicAdd(&g_pos[d], 1);
        g_esrc[p] = src[e];
    }
}

// ---------- W1 transpose + fp16 convert: g_Wt[n][k] = fp16(W1[k][n]) ----------
__global__ void k_wprep(const float* __restrict__ W1) {
    int tid = blockIdx.x * 256 + threadIdx.x;   // 16384
    int n = tid >> 7, k = tid & 127;
    g_Wt[n * DF + k] = __float2half(W1[(size_t)k * DF + n]);
}

// ---------- fp16 tensor-core GEMM1: g_hs = fp16(x @ W1) ----------
__device__ __forceinline__ void mma_f16(float* c, const unsigned* a, const unsigned* b) {
    asm volatile(
        "mma.sync.aligned.m16n8k16.row.col.f32.f16.f16.f32 "
        "{%0,%1,%2,%3}, {%4,%5,%6,%7}, {%8,%9}, {%0,%1,%2,%3};"
        : "+f"(c[0]), "+f"(c[1]), "+f"(c[2]), "+f"(c[3])
        : "r"(a[0]), "r"(a[1]), "r"(a[2]), "r"(a[3]), "r"(b[0]), "r"(b[1]));
}

#define XS_STR 40
#define WS_STR 136

__global__ __launch_bounds__(256, 2) void k_gemm1(const float* __restrict__ X) {
    __shared__ __half Xs[128][XS_STR];
    __shared__ __half Ws[128][WS_STR];

    const int t = threadIdx.x;
    const int m0 = blockIdx.x * 128;
    const int w = t >> 5, lane = t & 31;
    const int m0w = (w >> 2) * 64;
    const int n0w = (w & 3) * 32;
    const int lg = lane >> 2, lq = lane & 3;

#pragma unroll
    for (int i = 0; i < 8; i++) {
        int g = i * 256 + t;
        int row = g >> 4, c = (g & 15) * 8;
        *(uint4*)&Ws[row][c] = *(const uint4*)&g_Wt[row * DF + c];
    }

    float acc[4][4][4] = {};
    float4 pv[4];

    auto prefetch = [&](int kc) {
#pragma unroll
        for (int i = 0; i < 4; i++) {
            int g = i * 256 + t;
            int row = g >> 3, q = g & 7;
            int m = m0 + row;
            pv[i] = (m < NN) ? *(const float4*)&X[(size_t)m * DF + kc * 32 + q * 4]
                             : make_float4(0.f, 0.f, 0.f, 0.f);
        }
    };

    prefetch(0);
    __syncthreads();

    for (int kc = 0; kc < 4; kc++) {
#pragma unroll
        for (int i = 0; i < 4; i++) {
            int g = i * 256 + t;
            int row = g >> 3, q = g & 7;
            __half2 h0 = __floats2half2_rn(pv[i].x, pv[i].y);
            __half2 h1 = __floats2half2_rn(pv[i].z, pv[i].w);
            uint2 u;
            u.x = *(unsigned*)&h0;
            u.y = *(unsigned*)&h1;
            *(uint2*)&Xs[row][q * 4] = u;
        }
        __syncthreads();
        if (kc < 3) prefetch(kc + 1);

#pragma unroll
        for (int k0 = 0; k0 < 32; k0 += 16) {
            int kg = kc * 32 + k0;
            unsigned A[4][4], B[4][2];
#pragma unroll
            for (int mi = 0; mi < 4; mi++) {
                int mr = m0w + mi * 16 + lg;
                A[mi][0] = *(unsigned*)&Xs[mr][k0 + 2 * lq];
                A[mi][1] = *(unsigned*)&Xs[mr + 8][k0 + 2 * lq];
                A[mi][2] = *(unsigned*)&Xs[mr][k0 + 8 + 2 * lq];
                A[mi][3] = *(unsigned*)&Xs[mr + 8][k0 + 8 + 2 * lq];
            }
#pragma unroll
            for (int ni = 0; ni < 4; ni++) {
                int nc = n0w + ni * 8 + lg;
                B[ni][0] = *(unsigned*)&Ws[nc][kg + 2 * lq];
                B[ni][1] = *(unsigned*)&Ws[nc][kg + 8 + 2 * lq];
            }
#pragma unroll
            for (int mi = 0; mi < 4; mi++)
#pragma unroll
                for (int ni = 0; ni < 4; ni++)
                    mma_f16(acc[mi][ni], A[mi], B[ni]);
        }
        __syncthreads();
    }

#pragma unroll
    for (int mi = 0; mi < 4; mi++) {
        int r0 = m0 + m0w + mi * 16 + lg;
        int r1 = r0 + 8;
#pragma unroll
        for (int ni = 0; ni < 4; ni++) {
            int h2col = ((n0w + ni * 8) >> 1) + lq;
            if (r0 < NN)
                g_hs[(size_t)r0 * (DF / 2) + h2col] =
                    __floats2half2_rn(acc[mi][ni][0], acc[mi][ni][1]);
            if (r1 < NN)
                g_hs[(size_t)r1 * (DF / 2) + h2col] =
                    __floats2half2_rn(acc[mi][ni][2], acc[mi][ni][3]);
        }
    }
}

// ---------- fused gather-aggregate + relu + W2 GEMV (layer 1 -> gs) ----------
// TWO adjacent nodes per warp, interleaved edge streams (2x independent
// load chains per iteration). Shuffle-free uniform loads as in R13.
__global__ __launch_bounds__(256) void k_agg_mid(const float* __restrict__ b1,
                                                 const float* __restrict__ W2) {
    int gw = (blockIdx.x * 256 + threadIdx.x) >> 5;
    int lane = threadIdx.x & 31;
    int rA = gw * 2, rB = rA + 1;        // NN even -> rB < NN whenever rA < NN
    if (rA >= NN) return;

    const uint2* hsv = (const uint2*)g_hs;   // 32 uint2 per row
    float diA = g_dinv[rA];
    float diB = g_dinv[rB];

    uint2 svA = hsv[(size_t)rA * 32 + lane];
    uint2 svB = hsv[(size_t)rB * 32 + lane];
    float2 a0 = __half22float2(*(__half2*)&svA.x);
    float2 a1 = __half22float2(*(__half2*)&svA.y);
    float2 b0 = __half22float2(*(__half2*)&svB.x);
    float2 b1v = __half22float2(*(__half2*)&svB.y);
    float axA = a0.x * diA, ayA = a0.y * diA, azA = a1.x * diA, awA = a1.y * diA;
    float axB = b0.x * diB, ayB = b0.y * diB, azB = b1v.x * diB, awB = b1v.y * diB;

    int jA = g_rowstart[rA];
    int eA = jA + g_cnt[rA];
    int jB = eA;                          // CSR contiguity: start of rB == end of rA
    int eB = jB + g_cnt[rB];

    // interleaved main loop: one edge of each node per iteration
#pragma unroll 2
    for (; jA < eA && jB < eB; jA++, jB++) {
        int sA = __ldg(&g_esrc[jA]);
        int sB = __ldg(&g_esrc[jB]);
        float dA = __ldg(&g_dinv[sA]);
        float dB = __ldg(&g_dinv[sB]);
        uint2 vA = hsv[(size_t)sA * 32 + lane];
        uint2 vB = hsv[(size_t)sB * 32 + lane];
        float2 fA0 = __half22float2(*(__half2*)&vA.x);
        float2 fA1 = __half22float2(*(__half2*)&vA.y);
        float2 fB0 = __half22float2(*(__half2*)&vB.x);
        float2 fB1 = __half22float2(*(__half2*)&vB.y);
        axA = fmaf(fA0.x, dA, axA); ayA = fmaf(fA0.y, dA, ayA);
        azA = fmaf(fA1.x, dA, azA); awA = fmaf(fA1.y, dA, awA);
        axB = fmaf(fB0.x, dB, axB); ayB = fmaf(fB0.y, dB, ayB);
        azB = fmaf(fB1.x, dB, azB); awB = fmaf(fB1.y, dB, awB);
    }
#pragma unroll 2
    for (; jA < eA; jA++) {
        int s = __ldg(&g_esrc[jA]);
        float d = __ldg(&g_dinv[s]);
        uint2 v = hsv[(size_t)s * 32 + lane];
        float2 f0 = __half22float2(*(__half2*)&v.x);
        float2 f1 = __half22float2(*(__half2*)&v.y);
        axA = fmaf(f0.x, d, axA); ayA = fmaf(f0.y, d, ayA);
        azA = fmaf(f1.x, d, azA); awA = fmaf(f1.y, d, awA);
    }
#pragma unroll 2
    for (; jB < eB; jB++) {
        int s = __ldg(&g_esrc[jB]);
        float d = __ldg(&g_dinv[s]);
        uint2 v = hsv[(size_t)s * 32 + lane];
        float2 f0 = __half22float2(*(__half2*)&v.x);
        float2 f1 = __half22float2(*(__half2*)&v.y);
        axB = fmaf(f0.x, d, axB); ayB = fmaf(f0.y, d, ayB);
        azB = fmaf(f1.x, d, azB); awB = fmaf(f1.y, d, awB);
    }

    // epilogue for both nodes
    float4 bb = *(const float4*)&b1[lane * 4];
    float2 w0 = *(const float2*)&W2[(size_t)(lane * 4 + 0) * 2];
    float2 w1 = *(const float2*)&W2[(size_t)(lane * 4 + 1) * 2];
    float2 w2 = *(const float2*)&W2[(size_t)(lane * 4 + 2) * 2];
    float2 w3 = *(const float2*)&W2[(size_t)(lane * 4 + 3) * 2];

    float hA0 = fmaxf(fmaf(diA, axA, bb.x), 0.f);
    float hA1 = fmaxf(fmaf(diA, ayA, bb.y), 0.f);
    float hA2 = fmaxf(fmaf(diA, azA, bb.z), 0.f);
    float hA3 = fmaxf(fmaf(diA, awA, bb.w), 0.f);
    float hB0 = fmaxf(fmaf(diB, axB, bb.x), 0.f);
    float hB1 = fmaxf(fmaf(diB, ayB, bb.y), 0.f);
    float hB2 = fmaxf(fmaf(diB, azB, bb.z), 0.f);
    float hB3 = fmaxf(fmaf(diB, awB, bb.w), 0.f);

    float gxA = hA0 * w0.x + hA1 * w1.x + hA2 * w2.x + hA3 * w3.x;
    float gyA = hA0 * w0.y + hA1 * w1.y + hA2 * w2.y + hA3 * w3.y;
    float gxB = hB0 * w0.x + hB1 * w1.x + hB2 * w2.x + hB3 * w3.x;
    float gyB = hB0 * w0.y + hB1 * w1.y + hB2 * w2.y + hB3 * w3.y;
#pragma unroll
    for (int off = 16; off > 0; off >>= 1) {
        gxA += __shfl_xor_sync(FULLM, gxA, off);
        gyA += __shfl_xor_sync(FULLM, gyA, off);
        gxB += __shfl_xor_sync(FULLM, gxB, off);
        gyB += __shfl_xor_sync(FULLM, gyB, off);
    }
    if (lane == 0) {
        g_gs[rA] = make_float2(gxA * diA, gyA * diA);
        g_gs[rB] = make_float2(gxB * diB, gyB * diB);
    }
}

// ---------- layer-2 gather + bias -> out ----------
__global__ __launch_bounds__(256) void k_agg2(const float* __restrict__ b2,
                                              float* __restrict__ out) {
    int gt = blockIdx.x * 256 + threadIdx.x;
    int r = gt >> 5, lane = gt & 31;
    if (r >= NN) return;

    int start = g_rowstart[r];
    int len = g_cnt[r];
    float ax = 0.f, ay = 0.f;
    for (int j = lane; j < len; j += 32) {
        int s = g_esrc[start + j];
        float2 v = g_gs[s];
        ax += v.x; ay += v.y;
    }
#pragma unroll
    for (int off = 16; off > 0; off >>= 1) {
        ax += __shfl_xor_sync(FULLM, ax, off);
        ay += __shfl_xor_sync(FULLM, ay, off);
    }
    if (lane == 0) {
        float di = g_dinv[r];
        float2 self = g_gs[r];
        float2 o = make_float2(fmaf(di, self.x + ax, __ldg(&b2[0])),
                               fmaf(di, self.y + ay, __ldg(&b2[1])));
        *(float2*)&out[(size_t)r * 2] = o;
    }
}

extern "C" void kernel_launch(void* const* d_in, const int* in_sizes, int n_in,
                              void* d_out, int out_size) {
    const float* x  = (const float*)d_in[0];
    const int*   ei = (const int*)d_in[1];
    const float* W1 = (const float*)d_in[2];
    const float* b1 = (const float*)d_in[3];
    const float* W2 = (const float*)d_in[4];
    const float* b2 = (const float*)d_in[5];
    const int* src = ei;        // edge_index[0, :]
    const int* dst = ei + EE;   // edge_index[1, :]

    // fork point for side stream (GEMM branch independent of graph structure)
    cudaEventRecord(g_ev1, 0);
    cudaStreamWaitEvent(g_s2, g_ev1, 0);

    // submission order makes k_scan the 4th launch (ncu captures #4)
    k_zero_cnt<<<NB, 256>>>();                       // 1 (main)
    k_count<<<(EE + 255) / 256, 256>>>(dst);         // 2 (main)
    k_wprep<<<64, 256, 0, g_s2>>>(W1);               // 3 (s2)
    k_scan<<<NB, 256>>>();                           // 4 (main)  <- profiled
    k_gemm1<<<(NN + 127) / 128, 256, 0, g_s2>>>(x);  // 5 (s2)
    cudaEventRecord(g_ev2, g_s2);
    k_bin<<<(EE + 255) / 256, 256>>>(src, dst);      // 6 (main)

    // join, then fused aggregation (2 nodes per warp)
    cudaStreamWaitEvent(0, g_ev2, 0);
    k_agg_mid<<<(NN / 2 * 32 + 255) / 256, 256>>>(b1, W2);       // 7
    k_agg2<<<(NN * 32 + 255) / 256, 256>>>(b2, (float*)d_out);   // 8
}